// round 16
// baseline (speedup 1.0000x reference)
#include <cuda_runtime.h>
#include <cuda_fp16.h>
#include <cstdint>

#define NN 100000
#define EMAX 1600000

// ---------------- scratch (device globals; kernels reference them directly) -
__device__ __align__(256) int    g_deg[NN];
__device__ __align__(256) int    g_cnt[NN];
__device__ __align__(256) int    g_rowstart[NN + 1];
__device__ __align__(256) int    g_edge_src[EMAX];
__device__ __align__(256) float  g_agg[(size_t)NN * 128];
__device__ __align__(256) float  g_h[(size_t)NN * 128];
__device__ __align__(256) __half g_x16[(size_t)NN * 64];   // fp16 shadow of x
__device__ __align__(256) __half g_h16[(size_t)NN * 128];  // fp16 shadow of h

// ---------------- init ------------------------------------------------------
__global__ void zero_kernel() {
    int i = blockIdx.x * blockDim.x + threadIdx.x;
    if (i < NN) { g_deg[i] = 0; g_cnt[i] = 0; }
}

// ---------------- convert x -> fp16 shadow ----------------------------------
__global__ void cvt_x_kernel(const float* __restrict__ x) {
    int i = blockIdx.x * blockDim.x + threadIdx.x;  // half2 index
    if (i < NN * 32) {
        float2 f = ((const float2*)x)[i];
        ((__half2*)g_x16)[i] = __float22half2_rn(f);
    }
}

// ---------------- degree count (edge_index delivered as int32) --------------
__global__ void degree_kernel(const int* __restrict__ edge, int E) {
    int e = blockIdx.x * blockDim.x + threadIdx.x;
    if (e < E) {
        int dst = edge[(size_t)E + e];
        atomicAdd(&g_deg[dst], 1);
    }
}

// ---------------- exclusive scan of degrees (single block) ------------------
__global__ void scan_kernel() {
    __shared__ int warp_sums[32];
    __shared__ int s_carry;
    int tid = threadIdx.x, lane = tid & 31, wid = tid >> 5;
    if (tid == 0) s_carry = 0;
    __syncthreads();
    for (int base = 0; base < NN; base += 1024) {
        int i = base + tid;
        int v = (i < NN) ? g_deg[i] : 0;
        int x = v;
        #pragma unroll
        for (int off = 1; off < 32; off *= 2) {
            int t = __shfl_up_sync(0xffffffffu, x, off);
            if (lane >= off) x += t;
        }
        if (lane == 31) warp_sums[wid] = x;
        __syncthreads();
        if (wid == 0) {
            int w = warp_sums[lane];
            #pragma unroll
            for (int off = 1; off < 32; off *= 2) {
                int t = __shfl_up_sync(0xffffffffu, w, off);
                if (lane >= off) w += t;
            }
            warp_sums[lane] = w;
        }
        __syncthreads();
        int warp_off = (wid > 0) ? warp_sums[wid - 1] : 0;
        int incl = x + warp_off;
        int carry = s_carry;
        if (i < NN) g_rowstart[i] = carry + incl - v;
        __syncthreads();
        if (tid == 1023) s_carry = carry + incl;
        __syncthreads();
    }
    if (tid == 0) g_rowstart[NN] = s_carry;
}

// ---------------- scatter edges into CSR slots ------------------------------
__global__ void scatter_kernel(const int* __restrict__ edge, int E) {
    int e = blockIdx.x * blockDim.x + threadIdx.x;
    if (e < E) {
        int src = edge[e];
        int dst = edge[(size_t)E + e];
        int pos = g_rowstart[dst] + atomicAdd(&g_cnt[dst], 1);
        g_edge_src[pos] = src;
    }
}

// ---------------- aggregation D=64 (fp16 gather): half-warp per node --------
// Row = 64 halves = 16 uint2. Lane sl loads uint2 sl -> features [4sl..4sl+3].
__global__ void agg64_kernel() {
    int t = blockIdx.x * blockDim.x + threadIdx.x;
    int node = t >> 4;
    int sl   = t & 15;
    if (node >= NN) return;
    const uint2* feat = (const uint2*)g_x16;
    int s = g_rowstart[node];
    int e = g_rowstart[node + 1];

    float2 a0 = {0.f, 0.f}, b0 = {0.f, 0.f};   // even-edge acc (half2 #0, #1)
    float2 a1 = {0.f, 0.f}, b1 = {0.f, 0.f};   // odd-edge acc

    int i = s;
    for (; i + 4 <= e; i += 4) {
        int s0 = __ldg(&g_edge_src[i]);
        int s1 = __ldg(&g_edge_src[i + 1]);
        int s2 = __ldg(&g_edge_src[i + 2]);
        int s3 = __ldg(&g_edge_src[i + 3]);
        uint2 v0 = __ldg(&feat[(size_t)s0 * 16 + sl]);
        uint2 v1 = __ldg(&feat[(size_t)s1 * 16 + sl]);
        uint2 v2 = __ldg(&feat[(size_t)s2 * 16 + sl]);
        uint2 v3 = __ldg(&feat[(size_t)s3 * 16 + sl]);
        float2 f;
        f = __half22float2(*(const __half2*)&v0.x); a0.x += f.x; a0.y += f.y;
        f = __half22float2(*(const __half2*)&v0.y); b0.x += f.x; b0.y += f.y;
        f = __half22float2(*(const __half2*)&v1.x); a1.x += f.x; a1.y += f.y;
        f = __half22float2(*(const __half2*)&v1.y); b1.x += f.x; b1.y += f.y;
        f = __half22float2(*(const __half2*)&v2.x); a0.x += f.x; a0.y += f.y;
        f = __half22float2(*(const __half2*)&v2.y); b0.x += f.x; b0.y += f.y;
        f = __half22float2(*(const __half2*)&v3.x); a1.x += f.x; a1.y += f.y;
        f = __half22float2(*(const __half2*)&v3.y); b1.x += f.x; b1.y += f.y;
    }
    for (; i < e; i++) {
        int s0 = __ldg(&g_edge_src[i]);
        uint2 v0 = __ldg(&feat[(size_t)s0 * 16 + sl]);
        float2 f;
        f = __half22float2(*(const __half2*)&v0.x); a0.x += f.x; a0.y += f.y;
        f = __half22float2(*(const __half2*)&v0.y); b0.x += f.x; b0.y += f.y;
    }

    int deg = e - s;
    float inv = 1.0f / (float)(deg > 1 ? deg : 1);
    float4 r;
    r.x = (a0.x + a1.x) * inv;
    r.y = (a0.y + a1.y) * inv;
    r.z = (b0.x + b1.x) * inv;
    r.w = (b0.y + b1.y) * inv;
    ((float4*)(g_agg + (size_t)node * 64))[sl] = r;
}

// ---------------- aggregation D=128 (fp16 gather): warp per node ------------
// Row = 128 halves = 32 uint2. Lane loads uint2 lane -> features [4l..4l+3].
__global__ void agg128_kernel() {
    int warp = (blockIdx.x * blockDim.x + threadIdx.x) >> 5;
    int lane = threadIdx.x & 31;
    if (warp >= NN) return;
    const uint2* feat = (const uint2*)g_h16;
    int s = g_rowstart[warp];
    int e = g_rowstart[warp + 1];

    float2 a0 = {0.f, 0.f}, b0 = {0.f, 0.f};
    float2 a1 = {0.f, 0.f}, b1 = {0.f, 0.f};

    int i = s;
    for (; i + 4 <= e; i += 4) {
        int s0 = __ldg(&g_edge_src[i]);
        int s1 = __ldg(&g_edge_src[i + 1]);
        int s2 = __ldg(&g_edge_src[i + 2]);
        int s3 = __ldg(&g_edge_src[i + 3]);
        uint2 v0 = __ldg(&feat[(size_t)s0 * 32 + lane]);
        uint2 v1 = __ldg(&feat[(size_t)s1 * 32 + lane]);
        uint2 v2 = __ldg(&feat[(size_t)s2 * 32 + lane]);
        uint2 v3 = __ldg(&feat[(size_t)s3 * 32 + lane]);
        float2 f;
        f = __half22float2(*(const __half2*)&v0.x); a0.x += f.x; a0.y += f.y;
        f = __half22float2(*(const __half2*)&v0.y); b0.x += f.x; b0.y += f.y;
        f = __half22float2(*(const __half2*)&v1.x); a1.x += f.x; a1.y += f.y;
        f = __half22float2(*(const __half2*)&v1.y); b1.x += f.x; b1.y += f.y;
        f = __half22float2(*(const __half2*)&v2.x); a0.x += f.x; a0.y += f.y;
        f = __half22float2(*(const __half2*)&v2.y); b0.x += f.x; b0.y += f.y;
        f = __half22float2(*(const __half2*)&v3.x); a1.x += f.x; a1.y += f.y;
        f = __half22float2(*(const __half2*)&v3.y); b1.x += f.x; b1.y += f.y;
    }
    for (; i < e; i++) {
        int s0 = __ldg(&g_edge_src[i]);
        uint2 v0 = __ldg(&feat[(size_t)s0 * 32 + lane]);
        float2 f;
        f = __half22float2(*(const __half2*)&v0.x); a0.x += f.x; a0.y += f.y;
        f = __half22float2(*(const __half2*)&v0.y); b0.x += f.x; b0.y += f.y;
    }

    int deg = e - s;
    float inv = 1.0f / (float)(deg > 1 ? deg : 1);
    float4 r;
    r.x = (a0.x + a1.x) * inv;
    r.y = (a0.y + a1.y) * inv;
    r.z = (b0.x + b1.x) * inv;
    r.w = (b0.y + b1.y) * inv;
    ((float4*)(g_agg + (size_t)warp * 128))[lane] = r;
}

// ---------------- TF32 helpers ----------------------------------------------
__device__ __forceinline__ uint32_t f32_to_tf32(float f) {
    uint32_t r;
    asm("cvt.rna.tf32.f32 %0, %1;" : "=r"(r) : "f"(f));
    return r;
}

__device__ __forceinline__ void mma_tf32(
    float& c0, float& c1, float& c2, float& c3,
    uint32_t a0, uint32_t a1, uint32_t a2, uint32_t a3,
    uint32_t b0, uint32_t b1)
{
    asm volatile(
        "mma.sync.aligned.m16n8k8.row.col.f32.tf32.tf32.f32 "
        "{%0,%1,%2,%3}, {%4,%5,%6,%7}, {%8,%9}, {%0,%1,%2,%3};"
        : "+f"(c0), "+f"(c1), "+f"(c2), "+f"(c3)
        : "r"(a0), "r"(a1), "r"(a2), "r"(a3), "r"(b0), "r"(b1));
}

// ---------------- tensor-core GEMM: out = [agg|xmat] @ [Wl|Wr]^T + b --------
// OUT_TO_H: write fp32 to g_h AND fp16 shadow to g_h16 (layer 1).
template <int K, bool RELU, bool X_FROM_H, bool OUT_TO_H>
__global__ __launch_bounds__(256) void gemm_tc_kernel(
    const float* __restrict__ xparam,
    const float* __restrict__ Wl, const float* __restrict__ Wr,
    const float* __restrict__ bias, float* __restrict__ outparam)
{
    constexpr int KT = 32;
    __shared__ uint32_t As[128][36];
    __shared__ uint32_t Bs[128][36];

    const float* xmat = X_FROM_H ? (const float*)g_h : xparam;
    float* out = OUT_TO_H ? (float*)g_h : outparam;

    int tid  = threadIdx.x;
    int lane = tid & 31;
    int wid  = tid >> 5;
    int warp_m = wid & 3;
    int warp_n = wid >> 2;
    int rowbase = blockIdx.x * 128;

    int qrow = lane >> 2;
    int qcol = lane & 3;

    float acc[2][8][4];
    #pragma unroll
    for (int m = 0; m < 2; m++)
        #pragma unroll
        for (int n = 0; n < 8; n++)
            #pragma unroll
            for (int r = 0; r < 4; r++) acc[m][n][r] = 0.f;

    int st_row = tid >> 1;
    int st_kk  = (tid & 1) * 16;

    for (int kc = 0; kc < 2 * K; kc += KT) {
        bool first = (kc < K);
        const float* amat = first ? (const float*)g_agg : xmat;
        const float* wmat = first ? Wl : Wr;
        int kbase = first ? kc : kc - K;

        {
            int grow = rowbase + st_row;
            const float* ap = amat + (size_t)grow * K + kbase + st_kk;
            #pragma unroll
            for (int v = 0; v < 4; v++) {
                float4 f = (grow < NN) ? *(const float4*)(ap + v * 4)
                                       : make_float4(0.f, 0.f, 0.f, 0.f);
                As[st_row][st_kk + v * 4 + 0] = f32_to_tf32(f.x);
                As[st_row][st_kk + v * 4 + 1] = f32_to_tf32(f.y);
                As[st_row][st_kk + v * 4 + 2] = f32_to_tf32(f.z);
                As[st_row][st_kk + v * 4 + 3] = f32_to_tf32(f.w);
            }
        }
        {
            const float* wp = wmat + (size_t)st_row * K + kbase + st_kk;
            #pragma unroll
            for (int v = 0; v < 4; v++) {
                float4 f = *(const float4*)(wp + v * 4);
                Bs[st_row][st_kk + v * 4 + 0] = f32_to_tf32(f.x);
                Bs[st_row][st_kk + v * 4 + 1] = f32_to_tf32(f.y);
                Bs[st_row][st_kk + v * 4 + 2] = f32_to_tf32(f.z);
                Bs[st_row][st_kk + v * 4 + 3] = f32_to_tf32(f.w);
            }
        }
        __syncthreads();

        #pragma unroll
        for (int ks = 0; ks < KT; ks += 8) {
            uint32_t a[2][4];
            #pragma unroll
            for (int m = 0; m < 2; m++) {
                int r0 = warp_m * 32 + m * 16 + qrow;
                a[m][0] = As[r0][ks + qcol];
                a[m][1] = As[r0 + 8][ks + qcol];
                a[m][2] = As[r0][ks + 4 + qcol];
                a[m][3] = As[r0 + 8][ks + 4 + qcol];
            }
            #pragma unroll
            for (int n = 0; n < 8; n++) {
                int n0 = warp_n * 64 + n * 8 + qrow;
                uint32_t b0 = Bs[n0][ks + qcol];
                uint32_t b1 = Bs[n0][ks + 4 + qcol];
                #pragma unroll
                for (int m = 0; m < 2; m++)
                    mma_tf32(acc[m][n][0], acc[m][n][1], acc[m][n][2], acc[m][n][3],
                             a[m][0], a[m][1], a[m][2], a[m][3], b0, b1);
            }
        }
        __syncthreads();
    }

    // epilogue
    #pragma unroll
    for (int n = 0; n < 8; n++) {
        int cbase = warp_n * 64 + n * 8 + 2 * qcol;
        float bv0 = bias[cbase];
        float bv1 = bias[cbase + 1];
        #pragma unroll
        for (int m = 0; m < 2; m++) {
            int r0 = rowbase + warp_m * 32 + m * 16 + qrow;
            float v0 = acc[m][n][0] + bv0;
            float v1 = acc[m][n][1] + bv1;
            float v2 = acc[m][n][2] + bv0;
            float v3 = acc[m][n][3] + bv1;
            if (RELU) {
                v0 = v0 > 0.f ? v0 : 0.f;
                v1 = v1 > 0.f ? v1 : 0.f;
                v2 = v2 > 0.f ? v2 : 0.f;
                v3 = v3 > 0.f ? v3 : 0.f;
            }
            if (r0 < NN) {
                *(float2*)(out + (size_t)r0 * 128 + cbase) = make_float2(v0, v1);
                if (OUT_TO_H)
                    *(__half2*)(g_h16 + (size_t)r0 * 128 + cbase) =
                        __float22half2_rn(make_float2(v0, v1));
            }
            if (r0 + 8 < NN) {
                *(float2*)(out + (size_t)(r0 + 8) * 128 + cbase) = make_float2(v2, v3);
                if (OUT_TO_H)
                    *(__half2*)(g_h16 + (size_t)(r0 + 8) * 128 + cbase) =
                        __float22half2_rn(make_float2(v2, v3));
            }
        }
    }
}

// ---------------- launch ----------------------------------------------------
extern "C" void kernel_launch(void* const* d_in, const int* in_sizes, int n_in,
                              void* d_out, int out_size) {
    const float* x    = (const float*)d_in[0];
    const int*   edge = (const int*)d_in[1];     // int64 in reference, delivered as int32
    const float* W1l  = (const float*)d_in[2];
    const float* W1r  = (const float*)d_in[3];
    const float* b1   = (const float*)d_in[4];
    const float* W2l  = (const float*)d_in[5];
    const float* W2r  = (const float*)d_in[6];
    const float* b2   = (const float*)d_in[7];
    float* out = (float*)d_out;

    int E = in_sizes[1] / 2;

    // init + x fp16 shadow
    zero_kernel<<<(NN + 255) / 256, 256>>>();
    cvt_x_kernel<<<(NN * 32 + 255) / 256, 256>>>(x);

    // build CSR (by destination)
    degree_kernel<<<(E + 255) / 256, 256>>>(edge, E);
    scan_kernel<<<1, 1024>>>();
    scatter_kernel<<<(E + 255) / 256, 256>>>(edge, E);

    // layer 1: agg(x16) -> g_agg ; [g_agg|x] @ [W1l|W1r]^T + b1, relu -> g_h (+h16)
    agg64_kernel<<<(NN * 16 + 255) / 256, 256>>>();
    gemm_tc_kernel<64, true, false, true><<<(NN + 127) / 128, 256>>>(x, W1l, W1r, b1, nullptr);

    // layer 2: agg(h16) -> g_agg ; [g_agg|g_h] @ [W2l|W2r]^T + b2 -> out
    agg128_kernel<<<(NN * 32 + 255) / 256, 256>>>();
    gemm_tc_kernel<128, false, true, false><<<(NN + 127) / 128, 256>>>(nullptr, W2l, W2r, b2, out);
}

// round 17
// speedup vs baseline: 1.2397x; 1.2397x over previous
#include <cuda_runtime.h>
#include <cstdint>

#define NN 100000
#define EMAX 1600000
#define SCAN_BLK 1024
#define NBLKS ((NN + SCAN_BLK - 1) / SCAN_BLK)   // 98

// ---------------- scratch (device globals; kernels reference them directly) -
__device__ __align__(256) int   g_deg[NN];
__device__ __align__(256) int   g_cnt[NN];
__device__ __align__(256) int   g_rowstart[NN + 1];
__device__ __align__(256) int   g_edge_src[EMAX];
__device__ __align__(256) int   g_blocksum[NBLKS];
__device__ __align__(256) float g_agg[(size_t)NN * 128];
__device__ __align__(256) float g_h[(size_t)NN * 128];

// ---------------- init ------------------------------------------------------
__global__ void zero_kernel() {
    int i = blockIdx.x * blockDim.x + threadIdx.x;
    if (i < NN) { g_deg[i] = 0; g_cnt[i] = 0; }
}

// ---------------- degree count (edge_index delivered as int32) --------------
__global__ void degree_kernel(const int* __restrict__ edge, int E) {
    int e = blockIdx.x * blockDim.x + threadIdx.x;
    if (e < E) {
        int dst = edge[(size_t)E + e];
        atomicAdd(&g_deg[dst], 1);
    }
}

// ---------------- multi-block exclusive scan --------------------------------
// Phase 1: per-block local exclusive scan of g_deg -> g_rowstart; block sums.
__global__ __launch_bounds__(SCAN_BLK) void scan1_kernel() {
    __shared__ int warp_sums[32];
    int tid = threadIdx.x, lane = tid & 31, wid = tid >> 5;
    int i = blockIdx.x * SCAN_BLK + tid;
    int v = (i < NN) ? g_deg[i] : 0;
    int x = v;
    #pragma unroll
    for (int off = 1; off < 32; off *= 2) {
        int t = __shfl_up_sync(0xffffffffu, x, off);
        if (lane >= off) x += t;
    }
    if (lane == 31) warp_sums[wid] = x;
    __syncthreads();
    if (wid == 0) {
        int w = (lane < 32) ? warp_sums[lane] : 0;
        #pragma unroll
        for (int off = 1; off < 32; off *= 2) {
            int t = __shfl_up_sync(0xffffffffu, w, off);
            if (lane >= off) w += t;
        }
        warp_sums[lane] = w;
    }
    __syncthreads();
    int warp_off = (wid > 0) ? warp_sums[wid - 1] : 0;
    int incl = x + warp_off;
    if (i < NN) g_rowstart[i] = incl - v;     // block-local exclusive
    if (tid == SCAN_BLK - 1) g_blocksum[blockIdx.x] = incl;
}

// Phase 2: exclusive scan of the NBLKS block sums (single tiny block).
__global__ void scan2_kernel() {
    __shared__ int warp_sums[4];
    int tid = threadIdx.x, lane = tid & 31, wid = tid >> 5;  // 128 threads
    int v = (tid < NBLKS) ? g_blocksum[tid] : 0;
    int x = v;
    #pragma unroll
    for (int off = 1; off < 32; off *= 2) {
        int t = __shfl_up_sync(0xffffffffu, x, off);
        if (lane >= off) x += t;
    }
    if (lane == 31) warp_sums[wid] = x;
    __syncthreads();
    if (wid == 0 && lane < 4) {
        int w = warp_sums[lane];
        #pragma unroll
        for (int off = 1; off < 4; off *= 2) {
            int t = __shfl_up_sync(0xfu, w, off);
            if (lane >= off) w += t;
        }
        warp_sums[lane] = w;
    }
    __syncthreads();
    int warp_off = (wid > 0) ? warp_sums[wid - 1] : 0;
    if (tid < NBLKS) g_blocksum[tid] = x + warp_off - v;    // exclusive
}

// Phase 3: add block offsets; thread 0 writes rowstart[NN] = E.
__global__ __launch_bounds__(SCAN_BLK) void scan3_kernel(int E) {
    int i = blockIdx.x * SCAN_BLK + threadIdx.x;
    if (i < NN) g_rowstart[i] += g_blocksum[blockIdx.x];
    if (i == 0) g_rowstart[NN] = E;
}

// ---------------- scatter edges into CSR slots ------------------------------
__global__ void scatter_kernel(const int* __restrict__ edge, int E) {
    int e = blockIdx.x * blockDim.x + threadIdx.x;
    if (e < E) {
        int src = edge[e];
        int dst = edge[(size_t)E + e];
        int pos = g_rowstart[dst] + atomicAdd(&g_cnt[dst], 1);
        g_edge_src[pos] = src;
    }
}

// ---------------- aggregation D=64: half-warp (16 lanes) per node -----------
__global__ void agg64_kernel(const float* __restrict__ feat) {
    int t = blockIdx.x * blockDim.x + threadIdx.x;
    int node = t >> 4;
    int sl   = t & 15;
    if (node >= NN) return;
    int s = g_rowstart[node];
    int e = g_rowstart[node + 1];

    float4 acc0 = make_float4(0.f, 0.f, 0.f, 0.f);
    float4 acc1 = make_float4(0.f, 0.f, 0.f, 0.f);

    int i = s;
    for (; i + 4 <= e; i += 4) {
        int s0 = __ldg(&g_edge_src[i]);
        int s1 = __ldg(&g_edge_src[i + 1]);
        int s2 = __ldg(&g_edge_src[i + 2]);
        int s3 = __ldg(&g_edge_src[i + 3]);
        float4 v0 = __ldg((const float4*)(feat + (size_t)s0 * 64) + sl);
        float4 v1 = __ldg((const float4*)(feat + (size_t)s1 * 64) + sl);
        float4 v2 = __ldg((const float4*)(feat + (size_t)s2 * 64) + sl);
        float4 v3 = __ldg((const float4*)(feat + (size_t)s3 * 64) + sl);
        acc0.x += v0.x; acc0.y += v0.y; acc0.z += v0.z; acc0.w += v0.w;
        acc1.x += v1.x; acc1.y += v1.y; acc1.z += v1.z; acc1.w += v1.w;
        acc0.x += v2.x; acc0.y += v2.y; acc0.z += v2.z; acc0.w += v2.w;
        acc1.x += v3.x; acc1.y += v3.y; acc1.z += v3.z; acc1.w += v3.w;
    }
    for (; i < e; i++) {
        int s0 = __ldg(&g_edge_src[i]);
        float4 v0 = __ldg((const float4*)(feat + (size_t)s0 * 64) + sl);
        acc0.x += v0.x; acc0.y += v0.y; acc0.z += v0.z; acc0.w += v0.w;
    }

    int deg = e - s;
    float inv = 1.0f / (float)(deg > 1 ? deg : 1);
    float4 r;
    r.x = (acc0.x + acc1.x) * inv;
    r.y = (acc0.y + acc1.y) * inv;
    r.z = (acc0.z + acc1.z) * inv;
    r.w = (acc0.w + acc1.w) * inv;
    ((float4*)(g_agg + (size_t)node * 64))[sl] = r;
}

// ---------------- aggregation D=128: warp per node, float4 per lane ---------
__global__ void agg128_kernel() {
    int warp = (blockIdx.x * blockDim.x + threadIdx.x) >> 5;
    int lane = threadIdx.x & 31;
    if (warp >= NN) return;
    const float* feat = (const float*)g_h;
    int s = g_rowstart[warp];
    int e = g_rowstart[warp + 1];

    float4 acc0 = make_float4(0.f, 0.f, 0.f, 0.f);
    float4 acc1 = make_float4(0.f, 0.f, 0.f, 0.f);

    int i = s;
    for (; i + 4 <= e; i += 4) {
        int s0 = __ldg(&g_edge_src[i]);
        int s1 = __ldg(&g_edge_src[i + 1]);
        int s2 = __ldg(&g_edge_src[i + 2]);
        int s3 = __ldg(&g_edge_src[i + 3]);
        float4 v0 = __ldg((const float4*)(feat + (size_t)s0 * 128) + lane);
        float4 v1 = __ldg((const float4*)(feat + (size_t)s1 * 128) + lane);
        float4 v2 = __ldg((const float4*)(feat + (size_t)s2 * 128) + lane);
        float4 v3 = __ldg((const float4*)(feat + (size_t)s3 * 128) + lane);
        acc0.x += v0.x; acc0.y += v0.y; acc0.z += v0.z; acc0.w += v0.w;
        acc1.x += v1.x; acc1.y += v1.y; acc1.z += v1.z; acc1.w += v1.w;
        acc0.x += v2.x; acc0.y += v2.y; acc0.z += v2.z; acc0.w += v2.w;
        acc1.x += v3.x; acc1.y += v3.y; acc1.z += v3.z; acc1.w += v3.w;
    }
    for (; i < e; i++) {
        int s0 = __ldg(&g_edge_src[i]);
        float4 v0 = __ldg((const float4*)(feat + (size_t)s0 * 128) + lane);
        acc0.x += v0.x; acc0.y += v0.y; acc0.z += v0.z; acc0.w += v0.w;
    }

    int deg = e - s;
    float inv = 1.0f / (float)(deg > 1 ? deg : 1);
    float4 r;
    r.x = (acc0.x + acc1.x) * inv;
    r.y = (acc0.y + acc1.y) * inv;
    r.z = (acc0.z + acc1.z) * inv;
    r.w = (acc0.w + acc1.w) * inv;
    ((float4*)(g_agg + (size_t)warp * 128))[lane] = r;
}

// ---------------- TF32 helpers ----------------------------------------------
__device__ __forceinline__ uint32_t f32_to_tf32(float f) {
    uint32_t r;
    asm("cvt.rna.tf32.f32 %0, %1;" : "=r"(r) : "f"(f));
    return r;
}

__device__ __forceinline__ void mma_tf32(
    float& c0, float& c1, float& c2, float& c3,
    uint32_t a0, uint32_t a1, uint32_t a2, uint32_t a3,
    uint32_t b0, uint32_t b1)
{
    asm volatile(
        "mma.sync.aligned.m16n8k8.row.col.f32.tf32.tf32.f32 "
        "{%0,%1,%2,%3}, {%4,%5,%6,%7}, {%8,%9}, {%0,%1,%2,%3};"
        : "+f"(c0), "+f"(c1), "+f"(c2), "+f"(c3)
        : "r"(a0), "r"(a1), "r"(a2), "r"(a3), "r"(b0), "r"(b1));
}

// ---------------- tensor-core GEMM: out = [agg|xmat] @ [Wl|Wr]^T + b --------
template <int K, bool RELU, bool X_FROM_H, bool OUT_TO_H>
__global__ __launch_bounds__(256) void gemm_tc_kernel(
    const float* __restrict__ xparam,
    const float* __restrict__ Wl, const float* __restrict__ Wr,
    const float* __restrict__ bias, float* __restrict__ outparam)
{
    constexpr int KT = 32;
    __shared__ uint32_t As[128][36];
    __shared__ uint32_t Bs[128][36];

    const float* xmat = X_FROM_H ? (const float*)g_h : xparam;
    float* out = OUT_TO_H ? (float*)g_h : outparam;

    int tid  = threadIdx.x;
    int lane = tid & 31;
    int wid  = tid >> 5;
    int warp_m = wid & 3;
    int warp_n = wid >> 2;
    int rowbase = blockIdx.x * 128;

    int qrow = lane >> 2;
    int qcol = lane & 3;

    float acc[2][8][4];
    #pragma unroll
    for (int m = 0; m < 2; m++)
        #pragma unroll
        for (int n = 0; n < 8; n++)
            #pragma unroll
            for (int r = 0; r < 4; r++) acc[m][n][r] = 0.f;

    int st_row = tid >> 1;
    int st_kk  = (tid & 1) * 16;

    for (int kc = 0; kc < 2 * K; kc += KT) {
        bool first = (kc < K);
        const float* amat = first ? (const float*)g_agg : xmat;
        const float* wmat = first ? Wl : Wr;
        int kbase = first ? kc : kc - K;

        {
            int grow = rowbase + st_row;
            const float* ap = amat + (size_t)grow * K + kbase + st_kk;
            #pragma unroll
            for (int v = 0; v < 4; v++) {
                float4 f = (grow < NN) ? *(const float4*)(ap + v * 4)
                                       : make_float4(0.f, 0.f, 0.f, 0.f);
                As[st_row][st_kk + v * 4 + 0] = f32_to_tf32(f.x);
                As[st_row][st_kk + v * 4 + 1] = f32_to_tf32(f.y);
                As[st_row][st_kk + v * 4 + 2] = f32_to_tf32(f.z);
                As[st_row][st_kk + v * 4 + 3] = f32_to_tf32(f.w);
            }
        }
        {
            const float* wp = wmat + (size_t)st_row * K + kbase + st_kk;
            #pragma unroll
            for (int v = 0; v < 4; v++) {
                float4 f = *(const float4*)(wp + v * 4);
                Bs[st_row][st_kk + v * 4 + 0] = f32_to_tf32(f.x);
                Bs[st_row][st_kk + v * 4 + 1] = f32_to_tf32(f.y);
                Bs[st_row][st_kk + v * 4 + 2] = f32_to_tf32(f.z);
                Bs[st_row][st_kk + v * 4 + 3] = f32_to_tf32(f.w);
            }
        }
        __syncthreads();

        #pragma unroll
        for (int ks = 0; ks < KT; ks += 8) {
            uint32_t a[2][4];
            #pragma unroll
            for (int m = 0; m < 2; m++) {
                int r0 = warp_m * 32 + m * 16 + qrow;
                a[m][0] = As[r0][ks + qcol];
                a[m][1] = As[r0 + 8][ks + qcol];
                a[m][2] = As[r0][ks + 4 + qcol];
                a[m][3] = As[r0 + 8][ks + 4 + qcol];
            }
            #pragma unroll
            for (int n = 0; n < 8; n++) {
                int n0 = warp_n * 64 + n * 8 + qrow;
                uint32_t b0 = Bs[n0][ks + qcol];
                uint32_t b1 = Bs[n0][ks + 4 + qcol];
                #pragma unroll
                for (int m = 0; m < 2; m++)
                    mma_tf32(acc[m][n][0], acc[m][n][1], acc[m][n][2], acc[m][n][3],
                             a[m][0], a[m][1], a[m][2], a[m][3], b0, b1);
            }
        }
        __syncthreads();
    }

    // epilogue
    #pragma unroll
    for (int n = 0; n < 8; n++) {
        int cbase = warp_n * 64 + n * 8 + 2 * qcol;
        float bv0 = bias[cbase];
        float bv1 = bias[cbase + 1];
        #pragma unroll
        for (int m = 0; m < 2; m++) {
            int r0 = rowbase + warp_m * 32 + m * 16 + qrow;
            float v0 = acc[m][n][0] + bv0;
            float v1 = acc[m][n][1] + bv1;
            float v2 = acc[m][n][2] + bv0;
            float v3 = acc[m][n][3] + bv1;
            if (RELU) {
                v0 = v0 > 0.f ? v0 : 0.f;
                v1 = v1 > 0.f ? v1 : 0.f;
                v2 = v2 > 0.f ? v2 : 0.f;
                v3 = v3 > 0.f ? v3 : 0.f;
            }
            if (r0 < NN)
                *(float2*)(out + (size_t)r0 * 128 + cbase) = make_float2(v0, v1);
            if (r0 + 8 < NN)
                *(float2*)(out + (size_t)(r0 + 8) * 128 + cbase) = make_float2(v2, v3);
        }
    }
}

// ---------------- launch ----------------------------------------------------
extern "C" void kernel_launch(void* const* d_in, const int* in_sizes, int n_in,
                              void* d_out, int out_size) {
    const float* x    = (const float*)d_in[0];
    const int*   edge = (const int*)d_in[1];     // int64 in reference, delivered as int32
    const float* W1l  = (const float*)d_in[2];
    const float* W1r  = (const float*)d_in[3];
    const float* b1   = (const float*)d_in[4];
    const float* W2l  = (const float*)d_in[5];
    const float* W2r  = (const float*)d_in[6];
    const float* b2   = (const float*)d_in[7];
    float* out = (float*)d_out;

    int E = in_sizes[1] / 2;

    // build CSR (by destination)
    zero_kernel<<<(NN + 255) / 256, 256>>>();
    degree_kernel<<<(E + 255) / 256, 256>>>(edge, E);
    scan1_kernel<<<NBLKS, SCAN_BLK>>>();
    scan2_kernel<<<1, 128>>>();
    scan3_kernel<<<NBLKS, SCAN_BLK>>>(E);
    scatter_kernel<<<(E + 255) / 256, 256>>>(edge, E);

    // layer 1: agg(x) -> g_agg ; [g_agg|x] @ [W1l|W1r]^T + b1, relu -> g_h
    agg64_kernel<<<(NN * 16 + 255) / 256, 256>>>(x);
    gemm_tc_kernel<64, true, false, true><<<(NN + 127) / 128, 256>>>(x, W1l, W1r, b1, nullptr);

    // layer 2: agg(g_h) -> g_agg ; [g_agg|g_h] @ [W2l|W2r]^T + b2 -> out
    agg128_kernel<<<(NN * 32 + 255) / 256, 256>>>();
    gemm_tc_kernel<128, false, true, false><<<(NN + 127) / 128, 256>>>(nullptr, W2l, W2r, b2, out);
}